// round 9
// baseline (speedup 1.0000x reference)
#include <cuda_runtime.h>

#define BATCH   262144
#define NIND    32
#define NDEP    16
#define EPSV    1e-7f
#define ITERS   2

typedef unsigned long long u64;

// ---- packed f32x2 helpers (Blackwell sm_103a) ----
__device__ __forceinline__ u64 pack2(float a, float b) {
    u64 r; asm("mov.b64 %0, {%1, %2};" : "=l"(r) : "f"(a), "f"(b)); return r;
}
__device__ __forceinline__ u64 dup2(float a) {
    u64 r; asm("mov.b64 %0, {%1, %1};" : "=l"(r) : "f"(a)); return r;
}
__device__ __forceinline__ void unpack2(u64 v, float &a, float &b) {
    asm("mov.b64 {%0, %1}, %2;" : "=f"(a), "=f"(b) : "l"(v));
}
__device__ __forceinline__ u64 ffma2(u64 a, u64 b, u64 c) {
    u64 d; asm("fma.rn.f32x2 %0, %1, %2, %3;" : "=l"(d) : "l"(a), "l"(b), "l"(c));
    return d;
}
__device__ __forceinline__ u64 mul2(u64 a, u64 b) {
    u64 d; asm("mul.rn.f32x2 %0, %1, %2;" : "=l"(d) : "l"(a), "l"(b));
    return d;
}
__device__ __forceinline__ float frcp(float x) {
    float r; asm("rcp.approx.f32 %0, %1;" : "=f"(r) : "f"(x)); return r;
}

// Pre-transformed weights: row-paired u64 for direct f32x2 operands.
struct CWeights {
    ulonglong2 W2[2 * NIND][4];   // [k][q2]: rows (4q2..4q2+3) paired; k<32->Bmat, else Theta
    ulonglong2 L2[NIND][4];       // Lam
    ulonglong2 Off2[NDEP][4];     // column j, rows paired; +Gamma off-diag, 0 diag
    u64 Gd2[8];                   // (1+eps - Gamma_ii) pairs
    u64 Ups2[8];
};

__device__ CWeights g_scratch;    // written by prep kernel
__constant__ CWeights cw;         // copied from g_scratch before main kernel

// ---- prep kernel: transform raw weights into g_scratch layout ----
__global__ void prep_kernel(const float* __restrict__ Ups, const float* __restrict__ Bm,
                            const float* __restrict__ Th,  const float* __restrict__ Ga,
                            const float* __restrict__ La)
{
    const int tid = threadIdx.x;
    for (int idx = tid; idx < 2 * NIND * 8; idx += 64) {
        int k = idx >> 3, j2 = idx & 7;
        int r0 = 2 * j2, r1 = r0 + 1;
        float w0, w1;
        if (k < NIND) { w0 = Bm[r0 * NIND + k];          w1 = Bm[r1 * NIND + k]; }
        else          { w0 = Th[r0 * NIND + (k - NIND)]; w1 = Th[r1 * NIND + (k - NIND)]; }
        ((u64*)&g_scratch.W2[k][0])[j2] = pack2(w0, w1);
    }
    for (int idx = tid; idx < NIND * 8; idx += 64) {
        int k = idx >> 3, j2 = idx & 7;
        ((u64*)&g_scratch.L2[k][0])[j2] =
            pack2(La[(2 * j2) * NIND + k], La[(2 * j2 + 1) * NIND + k]);
    }
    for (int idx = tid; idx < NDEP * 8; idx += 64) {
        int j = idx >> 3, i2 = idx & 7;
        int i0 = 2 * i2, i1 = i0 + 1;
        float v0 = (i0 == j) ? 0.0f : Ga[i0 * NDEP + j];
        float v1 = (i1 == j) ? 0.0f : Ga[i1 * NDEP + j];
        ((u64*)&g_scratch.Off2[j][0])[i2] = pack2(v0, v1);
    }
    if (tid < 8) {
        g_scratch.Ups2[tid] = pack2(Ups[2 * tid], Ups[2 * tid + 1]);
        g_scratch.Gd2[tid]  = pack2(1.0f + EPSV - Ga[(2 * tid) * NDEP + 2 * tid],
                                    1.0f + EPSV - Ga[(2 * tid + 1) * NDEP + 2 * tid + 1]);
    }
}

#define ROWSTRIDE 33   // floats per staged row (conflict-free scalar access)
#define TPB       64   // threads per block
#define EPT       4    // elements per thread (amortizes the LDC port)

// Solve Neumann for TWO elements (row-packed f32x2), sharing Off2 LDC loads.
__device__ __forceinline__ void solve_pair(const u64* __restrict__ rhs0,
                                           const u64* __restrict__ dd0,
                                           const u64* __restrict__ rhs1,
                                           const u64* __restrict__ dd1,
                                           float* __restrict__ o0,
                                           float* __restrict__ o1)
{
    u64 inv0[8], inv1[8], y0[8], y1[8];
#pragma unroll
    for (int q = 0; q < 8; ++q) {
        float g0, g1; unpack2(cw.Gd2[q], g0, g1);
        float a0, a1, b0, b1;
        unpack2(dd0[q], a0, a1);
        unpack2(dd1[q], b0, b1);
        inv0[q] = pack2(frcp(g0 - a0), frcp(g1 - a1));
        inv1[q] = pack2(frcp(g0 - b0), frcp(g1 - b1));
        y0[q]   = mul2(inv0[q], rhs0[q]);
        y1[q]   = mul2(inv1[q], rhs1[q]);
    }
#pragma unroll
    for (int it = 0; it < ITERS; ++it) {
        u64 acc0[8], acc1[8];
#pragma unroll
        for (int q = 0; q < 8; ++q) { acc0[q] = rhs0[q]; acc1[q] = rhs1[q]; }
#pragma unroll
        for (int j = 0; j < NDEP; ++j) {
            float a0, a1; unpack2(y0[j >> 1], a0, a1);
            u64 yd0 = dup2((j & 1) ? a1 : a0);
            float b0, b1; unpack2(y1[j >> 1], b0, b1);
            u64 yd1 = dup2((j & 1) ? b1 : b0);
#pragma unroll
            for (int q2 = 0; q2 < 4; ++q2) {
                ulonglong2 o = cw.Off2[j][q2];
                acc0[2 * q2]     = ffma2(yd0, o.x, acc0[2 * q2]);
                acc0[2 * q2 + 1] = ffma2(yd0, o.y, acc0[2 * q2 + 1]);
                acc1[2 * q2]     = ffma2(yd1, o.x, acc1[2 * q2]);
                acc1[2 * q2 + 1] = ffma2(yd1, o.y, acc1[2 * q2 + 1]);
            }
        }
#pragma unroll
        for (int q = 0; q < 8; ++q) {
            y0[q] = mul2(inv0[q], acc0[q]);
            y1[q] = mul2(inv1[q], acc1[q]);
        }
    }
    ulonglong2* v0 = (ulonglong2*)o0;
    ulonglong2* v1 = (ulonglong2*)o1;
#pragma unroll
    for (int q = 0; q < 4; ++q) {
        v0[q] = make_ulonglong2(y0[2 * q], y0[2 * q + 1]);
        v1[q] = make_ulonglong2(y1[2 * q], y1[2 * q + 1]);
    }
}

// FOUR batch elements per thread; f32x2 packs OUTPUT ROWS (2i, 2i+1).
// Each constant-port LDC.128 weight load feeds FFMA2s for all 4 elements,
// cutting LDC-port cycles (floor 8/SMSP) ~2x vs 2-elem, ~4x vs 1-elem.
__global__ __launch_bounds__(TPB, 5)
void clefo_kernel(const float* __restrict__ X, const float* __restrict__ Z,
                  float* __restrict__ out)
{
    __shared__ float sStage[TPB * EPT * ROWSTRIDE]; // block slab of X or Z (reused)

    const int tid = threadIdx.x;
    const size_t base = (size_t)blockIdx.x * (TPB * EPT);

    // ---- stage X slab (coalesced global -> padded smem) ----
    {
        const float4* src = (const float4*)(X + base * NIND);
#pragma unroll
        for (int i = 0; i < 8 * EPT; ++i) {
            int idx = tid + TPB * i;                 // float4 index in slab
            float4 v = src[idx];
            int row = idx >> 3, c0 = (idx & 7) << 2;
            float* dst = &sStage[row * ROWSTRIDE + c0];
            dst[0] = v.x; dst[1] = v.y; dst[2] = v.z; dst[3] = v.w;
        }
    }
    __syncthreads();

    const float* row0 = &sStage[(tid          ) * ROWSTRIDE];
    const float* row1 = &sStage[(tid +     TPB) * ROWSTRIDE];
    const float* row2 = &sStage[(tid + 2 * TPB) * ROWSTRIDE];
    const float* row3 = &sStage[(tid + 3 * TPB) * ROWSTRIDE];

    // ---- Phase 1a: X-loop  (rhs += Bm*x ; d = La*x), rows packed in pairs
    u64 rhs[EPT][8], dd[EPT][8];
#pragma unroll
    for (int e = 0; e < EPT; ++e)
#pragma unroll
        for (int q = 0; q < 8; ++q) { rhs[e][q] = cw.Ups2[q]; dd[e][q] = 0ull; }

#pragma unroll 1
    for (int c = 0; c < NIND / 4; ++c) {
#pragma unroll
        for (int kk = 0; kk < 4; ++kk) {
            int k = 4 * c + kk;
            u64 xd0 = dup2(row0[k]);
            u64 xd1 = dup2(row1[k]);
            u64 xd2 = dup2(row2[k]);
            u64 xd3 = dup2(row3[k]);
#pragma unroll
            for (int q2 = 0; q2 < 4; ++q2) {
                ulonglong2 w = cw.W2[k][q2];
                rhs[0][2 * q2]     = ffma2(xd0, w.x, rhs[0][2 * q2]);
                rhs[0][2 * q2 + 1] = ffma2(xd0, w.y, rhs[0][2 * q2 + 1]);
                rhs[1][2 * q2]     = ffma2(xd1, w.x, rhs[1][2 * q2]);
                rhs[1][2 * q2 + 1] = ffma2(xd1, w.y, rhs[1][2 * q2 + 1]);
                rhs[2][2 * q2]     = ffma2(xd2, w.x, rhs[2][2 * q2]);
                rhs[2][2 * q2 + 1] = ffma2(xd2, w.y, rhs[2][2 * q2 + 1]);
                rhs[3][2 * q2]     = ffma2(xd3, w.x, rhs[3][2 * q2]);
                rhs[3][2 * q2 + 1] = ffma2(xd3, w.y, rhs[3][2 * q2 + 1]);
                ulonglong2 l = cw.L2[k][q2];
                dd[0][2 * q2]      = ffma2(xd0, l.x, dd[0][2 * q2]);
                dd[0][2 * q2 + 1]  = ffma2(xd0, l.y, dd[0][2 * q2 + 1]);
                dd[1][2 * q2]      = ffma2(xd1, l.x, dd[1][2 * q2]);
                dd[1][2 * q2 + 1]  = ffma2(xd1, l.y, dd[1][2 * q2 + 1]);
                dd[2][2 * q2]      = ffma2(xd2, l.x, dd[2][2 * q2]);
                dd[2][2 * q2 + 1]  = ffma2(xd2, l.y, dd[2][2 * q2 + 1]);
                dd[3][2 * q2]      = ffma2(xd3, l.x, dd[3][2 * q2]);
                dd[3][2 * q2 + 1]  = ffma2(xd3, l.y, dd[3][2 * q2 + 1]);
            }
        }
    }
    __syncthreads();

    // ---- stage Z slab (reuse buffer) ----
    {
        const float4* src = (const float4*)(Z + base * NIND);
#pragma unroll
        for (int i = 0; i < 8 * EPT; ++i) {
            int idx = tid + TPB * i;
            float4 v = src[idx];
            int r = idx >> 3, c0 = (idx & 7) << 2;
            float* dst = &sStage[r * ROWSTRIDE + c0];
            dst[0] = v.x; dst[1] = v.y; dst[2] = v.z; dst[3] = v.w;
        }
    }
    __syncthreads();

    // ---- Phase 1b: Z-loop  (rhs += Theta*z)
#pragma unroll 1
    for (int c = 0; c < NIND / 4; ++c) {
#pragma unroll
        for (int kk = 0; kk < 4; ++kk) {
            int kz = 4 * c + kk;
            int k  = NIND + kz;
            u64 xd0 = dup2(row0[kz]);
            u64 xd1 = dup2(row1[kz]);
            u64 xd2 = dup2(row2[kz]);
            u64 xd3 = dup2(row3[kz]);
#pragma unroll
            for (int q2 = 0; q2 < 4; ++q2) {
                ulonglong2 w = cw.W2[k][q2];
                rhs[0][2 * q2]     = ffma2(xd0, w.x, rhs[0][2 * q2]);
                rhs[0][2 * q2 + 1] = ffma2(xd0, w.y, rhs[0][2 * q2 + 1]);
                rhs[1][2 * q2]     = ffma2(xd1, w.x, rhs[1][2 * q2]);
                rhs[1][2 * q2 + 1] = ffma2(xd1, w.y, rhs[1][2 * q2 + 1]);
                rhs[2][2 * q2]     = ffma2(xd2, w.x, rhs[2][2 * q2]);
                rhs[2][2 * q2 + 1] = ffma2(xd2, w.y, rhs[2][2 * q2 + 1]);
                rhs[3][2 * q2]     = ffma2(xd3, w.x, rhs[3][2 * q2]);
                rhs[3][2 * q2 + 1] = ffma2(xd3, w.y, rhs[3][2 * q2 + 1]);
            }
        }
    }

    // ---- Phases 2+3: two pairs sequentially (keeps peak registers bounded)
    float* o0 = out + (base + tid) * NDEP;
    solve_pair(rhs[0], dd[0], rhs[1], dd[1],
               o0, o0 + (size_t)TPB * NDEP);
    solve_pair(rhs[2], dd[2], rhs[3], dd[3],
               o0 + (size_t)2 * TPB * NDEP, o0 + (size_t)3 * TPB * NDEP);
}

extern "C" void kernel_launch(void* const* d_in, const int* in_sizes, int n_in,
                              void* d_out, int out_size)
{
    const float* X  = (const float*)d_in[0];
    const float* Z  = (const float*)d_in[1];
    const float* Up = (const float*)d_in[2];
    const float* Bm = (const float*)d_in[3];
    const float* Th = (const float*)d_in[4];
    const float* Ga = (const float*)d_in[5];
    const float* La = (const float*)d_in[6];
    float* out = (float*)d_out;

    // 1) transform weights into device scratch
    prep_kernel<<<1, 64>>>(Up, Bm, Th, Ga, La);

    // 2) copy transformed weights into the constant bank (D2D, capturable)
    void* sp = nullptr;
    cudaGetSymbolAddress(&sp, g_scratch);
    cudaMemcpyToSymbolAsync(cw, sp, sizeof(CWeights), 0,
                            cudaMemcpyDeviceToDevice, 0);

    // 3) main kernel: four elements per thread
    const int blocks = BATCH / (TPB * EPT);
    clefo_kernel<<<blocks, TPB>>>(X, Z, out);
}

// round 10
// speedup vs baseline: 1.2058x; 1.2058x over previous
#include <cuda_runtime.h>

#define BATCH   262144
#define NIND    32
#define NDEP    16
#define EPSV    1e-7f
#define ITERS   2

typedef unsigned long long u64;

// ---- packed f32x2 helpers (Blackwell sm_103a) ----
__device__ __forceinline__ u64 pack2(float a, float b) {
    u64 r; asm("mov.b64 %0, {%1, %2};" : "=l"(r) : "f"(a), "f"(b)); return r;
}
__device__ __forceinline__ u64 dup2(float a) {
    u64 r; asm("mov.b64 %0, {%1, %1};" : "=l"(r) : "f"(a)); return r;
}
__device__ __forceinline__ void unpack2(u64 v, float &a, float &b) {
    asm("mov.b64 {%0, %1}, %2;" : "=f"(a), "=f"(b) : "l"(v));
}
__device__ __forceinline__ u64 ffma2(u64 a, u64 b, u64 c) {
    u64 d; asm("fma.rn.f32x2 %0, %1, %2, %3;" : "=l"(d) : "l"(a), "l"(b), "l"(c));
    return d;
}
__device__ __forceinline__ u64 mul2(u64 a, u64 b) {
    u64 d; asm("mul.rn.f32x2 %0, %1, %2;" : "=l"(d) : "l"(a), "l"(b));
    return d;
}
__device__ __forceinline__ float frcp(float x) {
    float r; asm("rcp.approx.f32 %0, %1;" : "=f"(r) : "f"(x)); return r;
}

// Pre-transformed weights: row-paired u64 for direct f32x2 operands.
// Off2 lives in SHARED at runtime (fed from g_scratch) — splits load traffic
// across the constant port (W2/L2) and the smem crossbar (Off2).
struct CWeights {
    ulonglong2 W2[2 * NIND][4];   // [k][q2]: rows (4q2..4q2+3) paired; k<32->Bmat, else Theta
    ulonglong2 L2[NIND][4];       // Lam
    ulonglong2 Off2[NDEP][4];     // column j, rows paired; +Gamma off-diag, 0 diag
    u64 Gd2[8];                   // (1+eps - Gamma_ii) pairs
    u64 Ups2[8];
};

__device__ CWeights g_scratch;    // written by prep kernel
__constant__ CWeights cw;         // copied from g_scratch before main kernel

// ---- prep kernel: transform raw weights into g_scratch layout ----
__global__ void prep_kernel(const float* __restrict__ Ups, const float* __restrict__ Bm,
                            const float* __restrict__ Th,  const float* __restrict__ Ga,
                            const float* __restrict__ La)
{
    const int tid = threadIdx.x;
    for (int idx = tid; idx < 2 * NIND * 8; idx += 64) {
        int k = idx >> 3, j2 = idx & 7;
        int r0 = 2 * j2, r1 = r0 + 1;
        float w0, w1;
        if (k < NIND) { w0 = Bm[r0 * NIND + k];          w1 = Bm[r1 * NIND + k]; }
        else          { w0 = Th[r0 * NIND + (k - NIND)]; w1 = Th[r1 * NIND + (k - NIND)]; }
        ((u64*)&g_scratch.W2[k][0])[j2] = pack2(w0, w1);
    }
    for (int idx = tid; idx < NIND * 8; idx += 64) {
        int k = idx >> 3, j2 = idx & 7;
        ((u64*)&g_scratch.L2[k][0])[j2] =
            pack2(La[(2 * j2) * NIND + k], La[(2 * j2 + 1) * NIND + k]);
    }
    for (int idx = tid; idx < NDEP * 8; idx += 64) {
        int j = idx >> 3, i2 = idx & 7;
        int i0 = 2 * i2, i1 = i0 + 1;
        float v0 = (i0 == j) ? 0.0f : Ga[i0 * NDEP + j];
        float v1 = (i1 == j) ? 0.0f : Ga[i1 * NDEP + j];
        ((u64*)&g_scratch.Off2[j][0])[i2] = pack2(v0, v1);
    }
    if (tid < 8) {
        g_scratch.Ups2[tid] = pack2(Ups[2 * tid], Ups[2 * tid + 1]);
        g_scratch.Gd2[tid]  = pack2(1.0f + EPSV - Ga[(2 * tid) * NDEP + 2 * tid],
                                    1.0f + EPSV - Ga[(2 * tid + 1) * NDEP + 2 * tid + 1]);
    }
}

#define ROWSTRIDE 33   // floats per staged row (conflict-free scalar access)
#define TPB       64   // threads per block
#define EPT       2    // elements per thread

// TWO batch elements per thread; f32x2 packs OUTPUT ROWS (2i, 2i+1).
// W2/L2 from __constant__ (LDC port), Off2 from shared (crossbar) — the two
// load ports run in parallel. All loops fully unrolled so ptxas pipelines
// the ~30cyc LDC/LDS latencies instead of exposing them.
__global__ __launch_bounds__(TPB, 6)
void clefo_kernel(const float* __restrict__ X, const float* __restrict__ Z,
                  const CWeights* __restrict__ gw,
                  float* __restrict__ out)
{
    __shared__ float sStage[TPB * EPT * ROWSTRIDE]; // block slab of X or Z (reused)
    __shared__ ulonglong2 sOff2[NDEP][4];           // Neumann weights on the crossbar

    const int tid = threadIdx.x;
    const size_t base = (size_t)blockIdx.x * (TPB * EPT);

    // ---- stage X slab + Off2 (coalesced global -> padded smem) ----
    {
        const float4* src = (const float4*)(X + base * NIND);
#pragma unroll
        for (int i = 0; i < 8 * EPT; ++i) {
            int idx = tid + TPB * i;                 // float4 index in slab
            float4 v = src[idx];
            int row = idx >> 3, c0 = (idx & 7) << 2;
            float* dst = &sStage[row * ROWSTRIDE + c0];
            dst[0] = v.x; dst[1] = v.y; dst[2] = v.z; dst[3] = v.w;
        }
        // 64 ulonglong2 = one per thread
        ((ulonglong2*)sOff2)[tid] = ((const ulonglong2*)gw->Off2)[tid];
    }
    __syncthreads();

    const float* row0 = &sStage[(tid      ) * ROWSTRIDE];
    const float* row1 = &sStage[(tid + TPB) * ROWSTRIDE];

    // ---- Phase 1a: X-loop  (rhs += Bm*x ; d = La*x), rows packed in pairs
    u64 rhs0[8], rhs1[8], dd0[8], dd1[8];
#pragma unroll
    for (int q = 0; q < 8; ++q) {
        rhs0[q] = cw.Ups2[q]; rhs1[q] = cw.Ups2[q];
        dd0[q] = 0ull;        dd1[q] = 0ull;
    }

#pragma unroll
    for (int k = 0; k < NIND; ++k) {
        u64 xd0 = dup2(row0[k]);
        u64 xd1 = dup2(row1[k]);
#pragma unroll
        for (int q2 = 0; q2 < 4; ++q2) {
            ulonglong2 w = cw.W2[k][q2];
            rhs0[2 * q2]     = ffma2(xd0, w.x, rhs0[2 * q2]);
            rhs0[2 * q2 + 1] = ffma2(xd0, w.y, rhs0[2 * q2 + 1]);
            rhs1[2 * q2]     = ffma2(xd1, w.x, rhs1[2 * q2]);
            rhs1[2 * q2 + 1] = ffma2(xd1, w.y, rhs1[2 * q2 + 1]);
            ulonglong2 l = cw.L2[k][q2];
            dd0[2 * q2]      = ffma2(xd0, l.x, dd0[2 * q2]);
            dd0[2 * q2 + 1]  = ffma2(xd0, l.y, dd0[2 * q2 + 1]);
            dd1[2 * q2]      = ffma2(xd1, l.x, dd1[2 * q2]);
            dd1[2 * q2 + 1]  = ffma2(xd1, l.y, dd1[2 * q2 + 1]);
        }
    }
    __syncthreads();

    // ---- stage Z slab (reuse buffer) ----
    {
        const float4* src = (const float4*)(Z + base * NIND);
#pragma unroll
        for (int i = 0; i < 8 * EPT; ++i) {
            int idx = tid + TPB * i;
            float4 v = src[idx];
            int r = idx >> 3, c0 = (idx & 7) << 2;
            float* dst = &sStage[r * ROWSTRIDE + c0];
            dst[0] = v.x; dst[1] = v.y; dst[2] = v.z; dst[3] = v.w;
        }
    }
    __syncthreads();

    // ---- Phase 1b: Z-loop  (rhs += Theta*z)
#pragma unroll
    for (int kz = 0; kz < NIND; ++kz) {
        int k = NIND + kz;
        u64 xd0 = dup2(row0[kz]);
        u64 xd1 = dup2(row1[kz]);
#pragma unroll
        for (int q2 = 0; q2 < 4; ++q2) {
            ulonglong2 w = cw.W2[k][q2];
            rhs0[2 * q2]     = ffma2(xd0, w.x, rhs0[2 * q2]);
            rhs0[2 * q2 + 1] = ffma2(xd0, w.y, rhs0[2 * q2 + 1]);
            rhs1[2 * q2]     = ffma2(xd1, w.x, rhs1[2 * q2]);
            rhs1[2 * q2 + 1] = ffma2(xd1, w.y, rhs1[2 * q2 + 1]);
        }
    }

    // ---- Phase 2: Dg_i = (1+eps - Gamma_ii) - d_i ; inv = 1/Dg ; y0 = inv*rhs
    u64 inv0[8], inv1[8], y0[8], y1[8];
#pragma unroll
    for (int q = 0; q < 8; ++q) {
        float g0, g1; unpack2(cw.Gd2[q], g0, g1);
        float a0, a1, b0, b1;
        unpack2(dd0[q], a0, a1);
        unpack2(dd1[q], b0, b1);
        inv0[q] = pack2(frcp(g0 - a0), frcp(g1 - a1));
        inv1[q] = pack2(frcp(g0 - b0), frcp(g1 - b1));
        y0[q]   = mul2(inv0[q], rhs0[q]);
        y1[q]   = mul2(inv1[q], rhs1[q]);
    }

    // ---- Phase 3: Neumann iterations  acc = rhs + GammaOff*y ; y = inv (*) acc
    // Off2 read from SMEM (crossbar) — parallel to nothing else here, cheap.
#pragma unroll
    for (int it = 0; it < ITERS; ++it) {
        u64 acc0[8], acc1[8];
#pragma unroll
        for (int q = 0; q < 8; ++q) { acc0[q] = rhs0[q]; acc1[q] = rhs1[q]; }
#pragma unroll
        for (int j = 0; j < NDEP; ++j) {
            float a0, a1; unpack2(y0[j >> 1], a0, a1);
            u64 yd0 = dup2((j & 1) ? a1 : a0);
            float b0, b1; unpack2(y1[j >> 1], b0, b1);
            u64 yd1 = dup2((j & 1) ? b1 : b0);
#pragma unroll
            for (int q2 = 0; q2 < 4; ++q2) {
                ulonglong2 o = sOff2[j][q2];
                acc0[2 * q2]     = ffma2(yd0, o.x, acc0[2 * q2]);
                acc0[2 * q2 + 1] = ffma2(yd0, o.y, acc0[2 * q2 + 1]);
                acc1[2 * q2]     = ffma2(yd1, o.x, acc1[2 * q2]);
                acc1[2 * q2 + 1] = ffma2(yd1, o.y, acc1[2 * q2 + 1]);
            }
        }
#pragma unroll
        for (int q = 0; q < 8; ++q) {
            y0[q] = mul2(inv0[q], acc0[q]);
            y1[q] = mul2(inv1[q], acc1[q]);
        }
    }

    // ---- Store: row-packed pairs are already in output order -> STG.128
    ulonglong2* v0 = (ulonglong2*)(out + (base + tid) * NDEP);
    ulonglong2* v1 = (ulonglong2*)(out + (base + TPB + tid) * NDEP);
#pragma unroll
    for (int q = 0; q < 4; ++q) {
        v0[q] = make_ulonglong2(y0[2 * q], y0[2 * q + 1]);
        v1[q] = make_ulonglong2(y1[2 * q], y1[2 * q + 1]);
    }
}

extern "C" void kernel_launch(void* const* d_in, const int* in_sizes, int n_in,
                              void* d_out, int out_size)
{
    const float* X  = (const float*)d_in[0];
    const float* Z  = (const float*)d_in[1];
    const float* Up = (const float*)d_in[2];
    const float* Bm = (const float*)d_in[3];
    const float* Th = (const float*)d_in[4];
    const float* Ga = (const float*)d_in[5];
    const float* La = (const float*)d_in[6];
    float* out = (float*)d_out;

    // 1) transform weights into device scratch
    prep_kernel<<<1, 64>>>(Up, Bm, Th, Ga, La);

    // 2) copy transformed weights into the constant bank (D2D, capturable)
    void* sp = nullptr;
    cudaGetSymbolAddress(&sp, g_scratch);
    cudaMemcpyToSymbolAsync(cw, sp, sizeof(CWeights), 0,
                            cudaMemcpyDeviceToDevice, 0);

    // 3) main kernel: two elements per thread, fine-grained grid (no wave tail)
    const int blocks = BATCH / (TPB * EPT);
    clefo_kernel<<<blocks, TPB>>>(X, Z, (const CWeights*)sp, out);
}